// round 1
// baseline (speedup 1.0000x reference)
#include <cuda_runtime.h>
#include <math.h>

#define B_  4
#define S_  2048
#define D_  1024
#define H_  16
#define DH_ 64

// Scratch for Q,K,V in [B,H,S,DH] layout (static device arrays: allocation-free).
__device__ float g_q[(size_t)B_ * H_ * S_ * DH_];
__device__ float g_k[(size_t)B_ * H_ * S_ * DH_];
__device__ float g_v[(size_t)B_ * H_ * S_ * DH_];

// ---------------------------------------------------------------------------
// Kernel 1: fused QKV projection.  out[m,n] = sum_k X[m,k] * W[n,k] + b[n]
// M = B*S = 8192, N = 1024, K = 1024.  grid.z in {0,1,2} selects Q/K/V.
// Block tile 64x64, K-tile 16, 256 threads, 4x4 register tile per thread.
// Output written directly in [B,H,S,DH] layout.
// ---------------------------------------------------------------------------
__global__ __launch_bounds__(256) void qkv_kernel(
    const float* __restrict__ X,
    const float* __restrict__ Wq, const float* __restrict__ Bq,
    const float* __restrict__ Wk, const float* __restrict__ Bk,
    const float* __restrict__ Wv, const float* __restrict__ Bv)
{
    __shared__ float As[16][68];   // [k][m], pad 68 to spread banks
    __shared__ float Bs[16][68];   // [k][n]

    const float* W;
    const float* bias;
    float* out;
    if (blockIdx.z == 0)      { W = Wq; bias = Bq; out = g_q; }
    else if (blockIdx.z == 1) { W = Wk; bias = Bk; out = g_k; }
    else                      { W = Wv; bias = Bv; out = g_v; }

    const int tid = threadIdx.x;
    const int tx = tid & 15;        // 0..15  (n direction)
    const int ty = tid >> 4;        // 0..15  (m direction)
    const int m0 = blockIdx.y * 64;
    const int n0 = blockIdx.x * 64;

    // Cooperative tile load mapping: 256 threads, each loads one float4 from A
    // and one from B per K-tile.
    const int lrow = tid >> 2;          // 0..63
    const int lk   = (tid & 3) << 2;    // 0,4,8,12

    const float* Aptr = X + (size_t)(m0 + lrow) * D_ + lk;
    const float* Bptr = W + (size_t)(n0 + lrow) * D_ + lk;

    float acc[4][4];
#pragma unroll
    for (int i = 0; i < 4; i++)
#pragma unroll
        for (int j = 0; j < 4; j++) acc[i][j] = 0.f;

    for (int k0 = 0; k0 < D_; k0 += 16) {
        float4 a = *(const float4*)(Aptr + k0);
        float4 w = *(const float4*)(Bptr + k0);
        As[lk + 0][lrow] = a.x;
        As[lk + 1][lrow] = a.y;
        As[lk + 2][lrow] = a.z;
        As[lk + 3][lrow] = a.w;
        Bs[lk + 0][lrow] = w.x;
        Bs[lk + 1][lrow] = w.y;
        Bs[lk + 2][lrow] = w.z;
        Bs[lk + 3][lrow] = w.w;
        __syncthreads();

#pragma unroll
        for (int kk = 0; kk < 16; kk++) {
            float4 av = *(const float4*)&As[kk][ty << 2];
            float4 bv = *(const float4*)&Bs[kk][tx << 2];
            float ar[4] = {av.x, av.y, av.z, av.w};
            float br[4] = {bv.x, bv.y, bv.z, bv.w};
#pragma unroll
            for (int i = 0; i < 4; i++)
#pragma unroll
                for (int j = 0; j < 4; j++)
                    acc[i][j] = fmaf(ar[i], br[j], acc[i][j]);
        }
        __syncthreads();
    }

    // Epilogue: add bias and scatter into [B,H,S,DH] layout.
#pragma unroll
    for (int i = 0; i < 4; i++) {
        const int m = m0 + (ty << 2) + i;
        const int bb = m >> 11;         // batch
        const int s  = m & (S_ - 1);    // seq pos
#pragma unroll
        for (int j = 0; j < 4; j++) {
            const int n = n0 + (tx << 2) + j;
            const int h = n >> 6;
            const int d = n & 63;
            out[((((size_t)bb * H_ + h) * S_ + s) << 6) + d] = acc[i][j] + bias[n];
        }
    }
}

// ---------------------------------------------------------------------------
// Kernel 2: flash attention, fp32.  One block per (batch, head, 64-query tile).
// 256 threads (16x16): each thread owns a 4x4 score tile and a 4(q)x4(d)
// output tile.  Online softmax with shfl-xor reductions over the 16-lane
// tx groups.  K tiles of 64 keys; P staged through SMEM for the PV GEMM.
// ---------------------------------------------------------------------------
#define ATTN_SMEM_FLOATS (2 * 64 * 68 + 2 * 64 * 64)
#define ATTN_SMEM_BYTES  (ATTN_SMEM_FLOATS * 4)

__global__ __launch_bounds__(256) void attn_kernel(float* __restrict__ out)
{
    extern __shared__ float sm[];
    float* Qts = sm;                       // [d=64][row pad 68], Q^T, pre-scaled
    float* Kts = sm + 64 * 68;             // [d=64][col pad 68], K^T
    float* Vs  = sm + 2 * 64 * 68;         // [k=64][d=64]
    float* Ps  = sm + 2 * 64 * 68 + 64 * 64; // [q=64][k=64]

    const int tid = threadIdx.x;
    const int tx = tid & 15;   // key-col / out-dim direction
    const int ty = tid >> 4;   // query-row direction
    const int qt = blockIdx.x;
    const int h  = blockIdx.y;
    const int b  = blockIdx.z;

    const float* Qg = g_q + (((size_t)b * H_ + h) * S_ + qt * 64) * DH_;
    const float* Kg = g_k + (((size_t)b * H_ + h) * S_) * DH_;
    const float* Vg = g_v + (((size_t)b * H_ + h) * S_) * DH_;

    const float scale = 0.125f;  // 1/sqrt(64)

    // Load Q tile transposed (d-major), folding in the softmax scale.
    for (int c = tid; c < 64 * 16; c += 256) {
        const int row = c >> 4;
        const int dc  = (c & 15) << 2;
        float4 v = *(const float4*)(Qg + (row << 6) + dc);
        Qts[(dc + 0) * 68 + row] = v.x * scale;
        Qts[(dc + 1) * 68 + row] = v.y * scale;
        Qts[(dc + 2) * 68 + row] = v.z * scale;
        Qts[(dc + 3) * 68 + row] = v.w * scale;
    }

    float m_i[4], l_i[4], o[4][4];
#pragma unroll
    for (int i = 0; i < 4; i++) {
        m_i[i] = -1e30f;
        l_i[i] = 0.f;
#pragma unroll
        for (int j = 0; j < 4; j++) o[i][j] = 0.f;
    }

    for (int kt = 0; kt < S_ / 64; kt++) {
        const float* Kt = Kg + ((size_t)kt << 6) * DH_;
        const float* Vt = Vg + ((size_t)kt << 6) * DH_;

        __syncthreads();   // prior iteration finished reading Kts/Vs/Ps
        for (int c = tid; c < 64 * 16; c += 256) {
            const int row = c >> 4;
            const int dc  = (c & 15) << 2;
            float4 kv = *(const float4*)(Kt + (row << 6) + dc);
            Kts[(dc + 0) * 68 + row] = kv.x;
            Kts[(dc + 1) * 68 + row] = kv.y;
            Kts[(dc + 2) * 68 + row] = kv.z;
            Kts[(dc + 3) * 68 + row] = kv.w;
            *(float4*)&Vs[(row << 6) + dc] = *(const float4*)(Vt + (row << 6) + dc);
        }
        __syncthreads();

        // ---- scores: S = (Q*scale) @ K^T,  4x4 per thread ----
        float s[4][4];
#pragma unroll
        for (int i = 0; i < 4; i++)
#pragma unroll
            for (int j = 0; j < 4; j++) s[i][j] = 0.f;

#pragma unroll 8
        for (int d = 0; d < 64; d++) {
            float4 qv = *(const float4*)&Qts[d * 68 + (ty << 2)];
            float4 kv = *(const float4*)&Kts[d * 68 + (tx << 2)];
            float qr[4] = {qv.x, qv.y, qv.z, qv.w};
            float kr[4] = {kv.x, kv.y, kv.z, kv.w};
#pragma unroll
            for (int i = 0; i < 4; i++)
#pragma unroll
                for (int j = 0; j < 4; j++)
                    s[i][j] = fmaf(qr[i], kr[j], s[i][j]);
        }

        // ---- online softmax (per query row, reduce over 16 tx lanes) ----
#pragma unroll
        for (int i = 0; i < 4; i++) {
            float mx = fmaxf(fmaxf(s[i][0], s[i][1]), fmaxf(s[i][2], s[i][3]));
            mx = fmaxf(mx, __shfl_xor_sync(0xffffffffu, mx, 1));
            mx = fmaxf(mx, __shfl_xor_sync(0xffffffffu, mx, 2));
            mx = fmaxf(mx, __shfl_xor_sync(0xffffffffu, mx, 4));
            mx = fmaxf(mx, __shfl_xor_sync(0xffffffffu, mx, 8));

            const float mnew = fmaxf(m_i[i], mx);
            const float corr = __expf(m_i[i] - mnew);
            m_i[i] = mnew;

            float rs = 0.f;
#pragma unroll
            for (int j = 0; j < 4; j++) {
                s[i][j] = __expf(s[i][j] - mnew);
                rs += s[i][j];
            }
            rs += __shfl_xor_sync(0xffffffffu, rs, 1);
            rs += __shfl_xor_sync(0xffffffffu, rs, 2);
            rs += __shfl_xor_sync(0xffffffffu, rs, 4);
            rs += __shfl_xor_sync(0xffffffffu, rs, 8);

            l_i[i] = l_i[i] * corr + rs;
#pragma unroll
            for (int j = 0; j < 4; j++) o[i][j] *= corr;

            *(float4*)&Ps[(((ty << 2) + i) << 6) + (tx << 2)] =
                make_float4(s[i][0], s[i][1], s[i][2], s[i][3]);
        }
        __syncthreads();

        // ---- O += P @ V  (contract over 64 keys, 4 at a time) ----
#pragma unroll 4
        for (int k4 = 0; k4 < 16; k4++) {
            float4 pv0 = *(const float4*)&Ps[(((ty << 2) + 0) << 6) + (k4 << 2)];
            float4 pv1 = *(const float4*)&Ps[(((ty << 2) + 1) << 6) + (k4 << 2)];
            float4 pv2 = *(const float4*)&Ps[(((ty << 2) + 2) << 6) + (k4 << 2)];
            float4 pv3 = *(const float4*)&Ps[(((ty << 2) + 3) << 6) + (k4 << 2)];
            float p0[4] = {pv0.x, pv0.y, pv0.z, pv0.w};
            float p1[4] = {pv1.x, pv1.y, pv1.z, pv1.w};
            float p2[4] = {pv2.x, pv2.y, pv2.z, pv2.w};
            float p3[4] = {pv3.x, pv3.y, pv3.z, pv3.w};
#pragma unroll
            for (int u = 0; u < 4; u++) {
                float4 vv = *(const float4*)&Vs[((((k4 << 2) + u)) << 6) + (tx << 2)];
                float vr[4] = {vv.x, vv.y, vv.z, vv.w};
#pragma unroll
                for (int j = 0; j < 4; j++) {
                    o[0][j] = fmaf(p0[u], vr[j], o[0][j]);
                    o[1][j] = fmaf(p1[u], vr[j], o[1][j]);
                    o[2][j] = fmaf(p2[u], vr[j], o[2][j]);
                    o[3][j] = fmaf(p3[u], vr[j], o[3][j]);
                }
            }
        }
    }

    // ---- epilogue: normalize and write [B,S,H,DH] = [B,S,D] ----
#pragma unroll
    for (int i = 0; i < 4; i++) {
        const float inv = 1.0f / l_i[i];
        const int srow = qt * 64 + (ty << 2) + i;
        float4 r = make_float4(o[i][0] * inv, o[i][1] * inv,
                               o[i][2] * inv, o[i][3] * inv);
        *(float4*)(out + ((((size_t)b * S_ + srow) * H_ + h) << 6) + (tx << 2)) = r;
    }
}

// ---------------------------------------------------------------------------
// Launch: inputs in metadata order:
//   0: hidden_states [4,2048,1024] f32
//   1: Wq [1024,1024]  2: bq [1024]
//   3: Wk              4: bk
//   5: Wv              6: bv
// Output: [4,2048,1024] f32
// ---------------------------------------------------------------------------
extern "C" void kernel_launch(void* const* d_in, const int* in_sizes, int n_in,
                              void* d_out, int out_size)
{
    const float* X  = (const float*)d_in[0];
    const float* Wq = (const float*)d_in[1];
    const float* bq = (const float*)d_in[2];
    const float* Wk = (const float*)d_in[3];
    const float* bk = (const float*)d_in[4];
    const float* Wv = (const float*)d_in[5];
    const float* bv = (const float*)d_in[6];
    float* out = (float*)d_out;

    (void)in_sizes; (void)n_in; (void)out_size;

    // QKV projection: grid (N/64, M/64, 3)
    dim3 g1(D_ / 64, (B_ * S_) / 64, 3);
    qkv_kernel<<<g1, 256>>>(X, Wq, bq, Wk, bk, Wv, bv);

    // Flash attention: grid (S/64 q-tiles, H, B), 67.5 KB dynamic smem.
    cudaFuncSetAttribute(attn_kernel,
                         cudaFuncAttributeMaxDynamicSharedMemorySize,
                         ATTN_SMEM_BYTES);
    dim3 g2(S_ / 64, H_, B_);
    attn_kernel<<<g2, 256, ATTN_SMEM_BYTES>>>(out);
}

// round 3
// speedup vs baseline: 3.0059x; 3.0059x over previous
#include <cuda_runtime.h>
#include <cuda_bf16.h>
#include <cstdint>
#include <math.h>

#define B_  4
#define S_  2048
#define D_  1024
#define H_  16
#define DH_ 64

// ---------------------------------------------------------------------------
// Static device scratch (allocation-free).
// ---------------------------------------------------------------------------
__device__ __nv_bfloat16 g_xhi[(size_t)B_ * S_ * D_];
__device__ __nv_bfloat16 g_xlo[(size_t)B_ * S_ * D_];
__device__ __nv_bfloat16 g_whi[(size_t)3 * D_ * D_];   // [Wq; Wk; Wv] rows
__device__ __nv_bfloat16 g_wlo[(size_t)3 * D_ * D_];

// Q/K/V in [B,H,S,DH], split bf16 (Q pre-scaled by 1/8).
__device__ __nv_bfloat16 g_qhi[(size_t)B_ * H_ * S_ * DH_];
__device__ __nv_bfloat16 g_qlo[(size_t)B_ * H_ * S_ * DH_];
__device__ __nv_bfloat16 g_khi[(size_t)B_ * H_ * S_ * DH_];
__device__ __nv_bfloat16 g_klo[(size_t)B_ * H_ * S_ * DH_];
__device__ __nv_bfloat16 g_vhi[(size_t)B_ * H_ * S_ * DH_];
__device__ __nv_bfloat16 g_vlo[(size_t)B_ * H_ * S_ * DH_];

// ---------------------------------------------------------------------------
// PTX helpers (all compute_103-PTX-safe: mma.sync / ldmatrix / cp.async)
// ---------------------------------------------------------------------------
__device__ __forceinline__ uint32_t smem_u32(const void* p) {
    uint32_t a;
    asm("{ .reg .u64 t; cvta.to.shared.u64 t, %1; cvt.u32.u64 %0, t; }"
        : "=r"(a) : "l"(p));
    return a;
}

#define MMA_BF16(d, a, b)                                                   \
    asm volatile(                                                           \
        "mma.sync.aligned.m16n8k16.row.col.f32.bf16.bf16.f32 "              \
        "{%0,%1,%2,%3}, {%4,%5,%6,%7}, {%8,%9}, {%0,%1,%2,%3};"             \
        : "+f"((d)[0]), "+f"((d)[1]), "+f"((d)[2]), "+f"((d)[3])            \
        : "r"((a)[0]), "r"((a)[1]), "r"((a)[2]), "r"((a)[3]),               \
          "r"((b)[0]), "r"((b)[1]))

#define LDSM_X4(r, addr)                                                    \
    asm volatile("ldmatrix.sync.aligned.m8n8.x4.shared.b16 "                \
                 "{%0,%1,%2,%3}, [%4];"                                     \
                 : "=r"((r)[0]), "=r"((r)[1]), "=r"((r)[2]), "=r"((r)[3])   \
                 : "r"(addr))

#define LDSM_X4T(r, addr)                                                   \
    asm volatile("ldmatrix.sync.aligned.m8n8.x4.trans.shared.b16 "          \
                 "{%0,%1,%2,%3}, [%4];"                                     \
                 : "=r"((r)[0]), "=r"((r)[1]), "=r"((r)[2]), "=r"((r)[3])   \
                 : "r"(addr))

#define CP_ASYNC16(dst, src) \
    asm volatile("cp.async.cg.shared.global [%0], [%1], 16;" :: "r"(dst), "l"(src))
#define CP_COMMIT() asm volatile("cp.async.commit_group;")
#define CP_WAIT1()  asm volatile("cp.async.wait_group 1;")
#define CP_WAIT0()  asm volatile("cp.async.wait_group 0;")

// Pack two floats as bf16x2 (hi) plus bf16x2 residuals (lo).
__device__ __forceinline__ void split2(float a, float b,
                                       uint32_t& hi, uint32_t& lo) {
    __nv_bfloat16 ha = __float2bfloat16(a);
    __nv_bfloat16 hb = __float2bfloat16(b);
    __nv_bfloat162 Hh = __halves2bfloat162(ha, hb);
    hi = *reinterpret_cast<uint32_t*>(&Hh);
    __nv_bfloat162 Ll = __floats2bfloat162_rn(a - __bfloat162float(ha),
                                              b - __bfloat162float(hb));
    lo = *reinterpret_cast<uint32_t*>(&Ll);
}

// ---------------------------------------------------------------------------
// Kernel 0: fp32 -> (hi, lo) bf16 split for X and W.
// ---------------------------------------------------------------------------
__global__ __launch_bounds__(256) void convert_kernel(
    const float* __restrict__ src,
    __nv_bfloat16* __restrict__ hi,
    __nv_bfloat16* __restrict__ lo)
{
    const size_t i = ((size_t)blockIdx.x * 256 + threadIdx.x) * 4;
    float4 x = *(const float4*)(src + i);
    uint32_t h0, l0, h1, l1;
    split2(x.x, x.y, h0, l0);
    split2(x.z, x.w, h1, l1);
    uint32_t* hp = (uint32_t*)(hi + i);
    uint32_t* lp = (uint32_t*)(lo + i);
    hp[0] = h0; hp[1] = h1;
    lp[0] = l0; lp[1] = l1;
}

// ---------------------------------------------------------------------------
// Kernel 1: QKV projection, mma.sync bf16 split-3.
// Block tile 128(M) x 128(N), BK=32, 256 threads (8 warps: 2 M x 4 N),
// warp tile 64x32.  cp.async double-buffered SMEM, pitch 80B.
// Epilogue: +bias, Q scaled by 1/8, emitted as split bf16 in [B,H,S,DH].
// ---------------------------------------------------------------------------
#define QP 40                         // smem pitch in bf16 elements (80B)
#define QKV_OFF_AHI 0
#define QKV_OFF_ALO 10240
#define QKV_OFF_BHI 20480
#define QKV_OFF_BLO 30720
#define QKV_STAGE   40960
#define QKV_SMEM    (2 * QKV_STAGE)

__global__ __launch_bounds__(256) void qkv_kernel(
    const float* __restrict__ bq,
    const float* __restrict__ bk,
    const float* __restrict__ bv)
{
    extern __shared__ char smc[];
    const uint32_t smb = smem_u32(smc);
    const int tid  = threadIdx.x;
    const int wid  = tid >> 5;
    const int lane = tid & 31;
    const int wm   = wid >> 2;        // 0..1
    const int wn   = wid & 3;         // 0..3
    const int m0 = blockIdx.y * 128;
    const int n0 = blockIdx.x * 128;

    const __nv_bfloat16* Ah = g_xhi + (size_t)m0 * D_;
    const __nv_bfloat16* Al = g_xlo + (size_t)m0 * D_;
    const __nv_bfloat16* Bh = g_whi + (size_t)n0 * D_;
    const __nv_bfloat16* Bl = g_wlo + (size_t)n0 * D_;

    // Per-thread load mapping: 512 16B-chunks per tensor per stage.
    const int lrow = tid >> 1;              // unused pattern placeholder
    (void)lrow;

    float acc[4][4][4];
#pragma unroll
    for (int a = 0; a < 4; a++)
#pragma unroll
        for (int b = 0; b < 4; b++)
#pragma unroll
            for (int c = 0; c < 4; c++) acc[a][b][c] = 0.f;

    // ldmatrix lane address components
    const int ra = (lane & 7) + ((lane >> 3) & 1) * 8;   // A row-in-tile
    const int ca = ((lane >> 4) & 1) * 16;               // A k-chunk byte
    const int rb = (lane & 7) + ((lane >> 4) & 1) * 8;   // B row (n) in pair
    const int cb = ((lane >> 3) & 1) * 16;               // B k-chunk byte

#define QKV_LOAD_STAGE(kc, s) do {                                          \
    const int _k0 = (kc) * 32;                                              \
    const uint32_t _st = smb + (s) * QKV_STAGE;                             \
    _Pragma("unroll")                                                       \
    for (int _i = 0; _i < 2; _i++) {                                        \
        const int _cid = _i * 256 + tid;                                    \
        const int _row = _cid >> 2;                                         \
        const int _ch  = _cid & 3;                                          \
        const uint32_t _d = _row * 80 + _ch * 16;                           \
        const size_t  _g = (size_t)_row * D_ + _k0 + _ch * 8;               \
        CP_ASYNC16(_st + QKV_OFF_AHI + _d, Ah + _g);                        \
        CP_ASYNC16(_st + QKV_OFF_ALO + _d, Al + _g);                        \
        CP_ASYNC16(_st + QKV_OFF_BHI + _d, Bh + _g);                        \
        CP_ASYNC16(_st + QKV_OFF_BLO + _d, Bl + _g);                        \
    }                                                                       \
    CP_COMMIT();                                                            \
} while (0)

    QKV_LOAD_STAGE(0, 0);

    for (int kc = 0; kc < 32; kc++) {
        const int s = kc & 1;
        if (kc + 1 < 32) {
            QKV_LOAD_STAGE(kc + 1, s ^ 1);
            CP_WAIT1();
        } else {
            CP_WAIT0();
        }
        __syncthreads();

        const uint32_t base = smb + s * QKV_STAGE;
#pragma unroll
        for (int ks = 0; ks < 2; ks++) {
            const int kb = ks * 32;
            uint32_t af[4][4], bf[2][4], xf[4][4];
#pragma unroll
            for (int mt = 0; mt < 4; mt++)
                LDSM_X4(af[mt], base + QKV_OFF_AHI +
                        (uint32_t)(wm * 64 + mt * 16 + ra) * 80 + kb + ca);
#pragma unroll
            for (int p = 0; p < 2; p++)
                LDSM_X4(bf[p], base + QKV_OFF_BHI +
                        (uint32_t)(wn * 32 + p * 16 + rb) * 80 + kb + cb);
            // hi*hi
#pragma unroll
            for (int mt = 0; mt < 4; mt++)
#pragma unroll
                for (int p = 0; p < 2; p++) {
                    MMA_BF16(acc[mt][2 * p],     af[mt], &bf[p][0]);
                    MMA_BF16(acc[mt][2 * p + 1], af[mt], &bf[p][2]);
                }
            // lo*hi
#pragma unroll
            for (int mt = 0; mt < 4; mt++)
                LDSM_X4(xf[mt], base + QKV_OFF_ALO +
                        (uint32_t)(wm * 64 + mt * 16 + ra) * 80 + kb + ca);
#pragma unroll
            for (int mt = 0; mt < 4; mt++)
#pragma unroll
                for (int p = 0; p < 2; p++) {
                    MMA_BF16(acc[mt][2 * p],     xf[mt], &bf[p][0]);
                    MMA_BF16(acc[mt][2 * p + 1], xf[mt], &bf[p][2]);
                }
            // hi*lo
#pragma unroll
            for (int p = 0; p < 2; p++)
                LDSM_X4(bf[p], base + QKV_OFF_BLO +
                        (uint32_t)(wn * 32 + p * 16 + rb) * 80 + kb + cb);
#pragma unroll
            for (int mt = 0; mt < 4; mt++)
#pragma unroll
                for (int p = 0; p < 2; p++) {
                    MMA_BF16(acc[mt][2 * p],     af[mt], &bf[p][0]);
                    MMA_BF16(acc[mt][2 * p + 1], af[mt], &bf[p][2]);
                }
        }
        __syncthreads();
    }

    // ---- Epilogue ----
    const int seg = n0 >> 10;                       // 0=Q 1=K 2=V
    const float* bias = (seg == 0) ? bq : (seg == 1) ? bk : bv;
    __nv_bfloat16* ohi = (seg == 0) ? g_qhi : (seg == 1) ? g_khi : g_vhi;
    __nv_bfloat16* olo = (seg == 0) ? g_qlo : (seg == 1) ? g_klo : g_vlo;
    const float scale = (seg == 0) ? 0.125f : 1.0f;

    const int r  = lane >> 2;
    const int c2 = (lane & 3) * 2;
#pragma unroll
    for (int mt = 0; mt < 4; mt++)
#pragma unroll
        for (int nt = 0; nt < 4; nt++) {
            const int nl = ((n0 & 1023) + wn * 32 + nt * 8 + c2);
            const int hh = nl >> 6;
            const int dd = nl & 63;
            const float b0v = __ldg(bias + nl);
            const float b1v = __ldg(bias + nl + 1);
#pragma unroll
            for (int half = 0; half < 2; half++) {
                const int m  = m0 + wm * 64 + mt * 16 + r + half * 8;
                const int bb = m >> 11;
                const int sp = m & (S_ - 1);
                const float v0 = (acc[mt][nt][2 * half + 0] + b0v) * scale;
                const float v1 = (acc[mt][nt][2 * half + 1] + b1v) * scale;
                uint32_t hi, lo;
                split2(v0, v1, hi, lo);
                const size_t addr =
                    ((((size_t)bb * H_ + hh) * S_ + sp) << 6) + dd;
                *(uint32_t*)(ohi + addr) = hi;
                *(uint32_t*)(olo + addr) = lo;
            }
        }
}

// ---------------------------------------------------------------------------
// Kernel 2: flash attention with mma.sync bf16 split-3.
// Block: (b, h, 64-query tile), 128 threads (4 warps, 16 q-rows each).
// Q frags hoisted in registers; P formed in registers from C frags.
// SMEM tiles pitch 72 elems (144B) -> conflict-free ldmatrix.
// ---------------------------------------------------------------------------
#define AP 72
#define AT_QHI 0
#define AT_QLO 9216
#define AT_KHI 18432
#define AT_KLO 27648
#define AT_VHI 36864
#define AT_VLO 46080
#define ATTN_SMEM 55296

__global__ __launch_bounds__(128) void attn_kernel(float* __restrict__ out)
{
    extern __shared__ char smc[];
    const uint32_t smb = smem_u32(smc);
    const int tid  = threadIdx.x;
    const int wid  = tid >> 5;
    const int lane = tid & 31;
    const int qt = blockIdx.x;
    const int h  = blockIdx.y;
    const int b  = blockIdx.z;

    const size_t hb = (((size_t)b * H_ + h) * S_) << 6;
    const __nv_bfloat16* qh = g_qhi + hb + ((size_t)qt << 12);
    const __nv_bfloat16* ql = g_qlo + hb + ((size_t)qt << 12);
    const __nv_bfloat16* kh = g_khi + hb;
    const __nv_bfloat16* kl = g_klo + hb;
    const __nv_bfloat16* vh = g_vhi + hb;
    const __nv_bfloat16* vl = g_vlo + hb;

    // ---- load Q tile (hi/lo) into SMEM ----
#pragma unroll
    for (int i = 0; i < 4; i++) {
        const int cid = i * 128 + tid;       // 512 chunks of 16B
        const int row = cid >> 3;
        const int ch  = cid & 7;
        *(uint4*)(smc + AT_QHI + row * 144 + ch * 16) =
            *(const uint4*)(qh + (row << 6) + ch * 8);
        *(uint4*)(smc + AT_QLO + row * 144 + ch * 16) =
            *(const uint4*)(ql + (row << 6) + ch * 8);
    }
    __syncthreads();

    // ---- hoist Q fragments (loop-invariant) ----
    const int ra = (lane & 7) + ((lane >> 3) & 1) * 8;
    const int ca = ((lane >> 4) & 1) * 16;
    uint32_t qfh[4][4], qfl[4][4];
#pragma unroll
    for (int t = 0; t < 4; t++) {
        const uint32_t off = (uint32_t)(wid * 16 + ra) * 144 + t * 32 + ca;
        LDSM_X4(qfh[t], smb + AT_QHI + off);
        LDSM_X4(qfl[t], smb + AT_QLO + off);
    }

    float o[8][4];
#pragma unroll
    for (int j = 0; j < 8; j++)
#pragma unroll
        for (int c = 0; c < 4; c++) o[j][c] = 0.f;
    float m0 = -1e30f, m1 = -1e30f, l0 = 0.f, l1 = 0.f;

    const int rb = (lane & 7) + ((lane >> 4) & 1) * 8;   // K n-row in pair
    const int cbk = ((lane >> 3) & 1) * 16;              // K k-chunk byte
    const int rv = (lane & 7) + ((lane >> 3) & 1) * 8;   // V key row
    const int cv = ((lane >> 4) & 1) * 16;               // V dh-tile byte in pair

    for (int kt = 0; kt < 32; kt++) {
        __syncthreads();
        const __nv_bfloat16* khp = kh + ((size_t)kt << 12);
        const __nv_bfloat16* klp = kl + ((size_t)kt << 12);
        const __nv_bfloat16* vhp = vh + ((size_t)kt << 12);
        const __nv_bfloat16* vlp = vl + ((size_t)kt << 12);
#pragma unroll
        for (int i = 0; i < 4; i++) {
            const int cid = i * 128 + tid;
            const int row = cid >> 3;
            const int ch  = cid & 7;
            const int d   = row * 144 + ch * 16;
            const size_t g = ((size_t)row << 6) + ch * 8;
            *(uint4*)(smc + AT_KHI + d) = *(const uint4*)(khp + g);
            *(uint4*)(smc + AT_KLO + d) = *(const uint4*)(klp + g);
            *(uint4*)(smc + AT_VHI + d) = *(const uint4*)(vhp + g);
            *(uint4*)(smc + AT_VLO + d) = *(const uint4*)(vlp + g);
        }
        __syncthreads();

        // ---- scores ----
        float sc[8][4];
#pragma unroll
        for (int j = 0; j < 8; j++)
#pragma unroll
            for (int c = 0; c < 4; c++) sc[j][c] = 0.f;

#pragma unroll
        for (int t = 0; t < 4; t++) {
            uint32_t kf[4][4];
#pragma unroll
            for (int p = 0; p < 4; p++)
                LDSM_X4(kf[p], smb + AT_KHI +
                        (uint32_t)(16 * p + rb) * 144 + t * 32 + cbk);
#pragma unroll
            for (int p = 0; p < 4; p++) {
                MMA_BF16(sc[2 * p],     qfh[t], &kf[p][0]);
                MMA_BF16(sc[2 * p + 1], qfh[t], &kf[p][2]);
                MMA_BF16(sc[2 * p],     qfl[t], &kf[p][0]);
                MMA_BF16(sc[2 * p + 1], qfl[t], &kf[p][2]);
            }
#pragma unroll
            for (int p = 0; p < 4; p++)
                LDSM_X4(kf[p], smb + AT_KLO +
                        (uint32_t)(16 * p + rb) * 144 + t * 32 + cbk);
#pragma unroll
            for (int p = 0; p < 4; p++) {
                MMA_BF16(sc[2 * p],     qfh[t], &kf[p][0]);
                MMA_BF16(sc[2 * p + 1], qfh[t], &kf[p][2]);
            }
        }

        // ---- online softmax (rows r=lane/4 and r+8) ----
        float rm0 = -1e30f, rm1 = -1e30f;
#pragma unroll
        for (int j = 0; j < 8; j++) {
            rm0 = fmaxf(rm0, fmaxf(sc[j][0], sc[j][1]));
            rm1 = fmaxf(rm1, fmaxf(sc[j][2], sc[j][3]));
        }
        rm0 = fmaxf(rm0, __shfl_xor_sync(0xffffffffu, rm0, 1));
        rm0 = fmaxf(rm0, __shfl_xor_sync(0xffffffffu, rm0, 2));
        rm1 = fmaxf(rm1, __shfl_xor_sync(0xffffffffu, rm1, 1));
        rm1 = fmaxf(rm1, __shfl_xor_sync(0xffffffffu, rm1, 2));

        const float mn0 = fmaxf(m0, rm0);
        const float mn1 = fmaxf(m1, rm1);
        const float cr0 = __expf(m0 - mn0);
        const float cr1 = __expf(m1 - mn1);
        m0 = mn0; m1 = mn1;

        float s0 = 0.f, s1 = 0.f;
#pragma unroll
        for (int j = 0; j < 8; j++) {
            sc[j][0] = __expf(sc[j][0] - mn0); s0 += sc[j][0];
            sc[j][1] = __expf(sc[j][1] - mn0); s0 += sc[j][1];
            sc[j][2] = __expf(sc[j][2] - mn1); s1 += sc[j][2];
            sc[j][3] = __expf(sc[j][3] - mn1); s1 += sc[j][3];
        }
        s0 += __shfl_xor_sync(0xffffffffu, s0, 1);
        s0 += __shfl_xor_sync(0xffffffffu, s0, 2);
        s1 += __shfl_xor_sync(0xffffffffu, s1, 1);
        s1 += __shfl_xor_sync(0xffffffffu, s1, 2);
        l0 = l0 * cr0 + s0;
        l1 = l1 * cr1 + s1;
#pragma unroll
        for (int j = 0; j < 8; j++) {
            o[j][0] *= cr0; o[j][1] *= cr0;
            o[j][2] *= cr1; o[j][3] *= cr1;
        }

        // ---- pack P into A-fragments (registers only) ----
        uint32_t ph[4][4], pl[4][4];
#pragma unroll
        for (int t = 0; t < 4; t++) {
            split2(sc[2 * t][0],     sc[2 * t][1],     ph[t][0], pl[t][0]);
            split2(sc[2 * t][2],     sc[2 * t][3],     ph[t][1], pl[t][1]);
            split2(sc[2 * t + 1][0], sc[2 * t + 1][1], ph[t][2], pl[t][2]);
            split2(sc[2 * t + 1][2], sc[2 * t + 1][3], ph[t][3], pl[t][3]);
        }

        // ---- O += P @ V ----
#pragma unroll
        for (int t = 0; t < 4; t++) {
            uint32_t vf[4][4];
#pragma unroll
            for (int p = 0; p < 4; p++)
                LDSM_X4T(vf[p], smb + AT_VHI +
                         (uint32_t)(16 * t + rv) * 144 + (2 * p) * 16 + cv);
#pragma unroll
            for (int p = 0; p < 4; p++) {
                MMA_BF16(o[2 * p],     ph[t], &vf[p][0]);
                MMA_BF16(o[2 * p + 1], ph[t], &vf[p][2]);
                MMA_BF16(o[2 * p],     pl[t], &vf[p][0]);
                MMA_BF16(o[2 * p + 1], pl[t], &vf[p][2]);
            }
#pragma unroll
            for (int p = 0; p < 4; p++)
                LDSM_X4T(vf[p], smb + AT_VLO +
                         (uint32_t)(16 * t + rv) * 144 + (2 * p) * 16 + cv);
#pragma unroll
            for (int p = 0; p < 4; p++) {
                MMA_BF16(o[2 * p],     ph[t], &vf[p][0]);
                MMA_BF16(o[2 * p + 1], ph[t], &vf[p][2]);
            }
        }
    }

    // ---- epilogue ----
    const float inv0 = 1.0f / l0;
    const float inv1 = 1.0f / l1;
    const int r  = lane >> 2;
    const int c2 = (lane & 3) * 2;
    const int q0 = qt * 64 + wid * 16 + r;
#pragma unroll
    for (int j = 0; j < 8; j++) {
        const int dh = j * 8 + c2;
        float2 v0 = make_float2(o[j][0] * inv0, o[j][1] * inv0);
        float2 v1 = make_float2(o[j][2] * inv1, o[j][3] * inv1);
        *(float2*)(out + ((size_t)b * S_ + q0) * D_ + h * 64 + dh) = v0;
        *(float2*)(out + ((size_t)b * S_ + q0 + 8) * D_ + h * 64 + dh) = v1;
    }
}

// ---------------------------------------------------------------------------
// Launch.
// ---------------------------------------------------------------------------
extern "C" void kernel_launch(void* const* d_in, const int* in_sizes, int n_in,
                              void* d_out, int out_size)
{
    const float* X  = (const float*)d_in[0];
    const float* Wq = (const float*)d_in[1];
    const float* bq = (const float*)d_in[2];
    const float* Wk = (const float*)d_in[3];
    const float* bk = (const float*)d_in[4];
    const float* Wv = (const float*)d_in[5];
    const float* bv = (const float*)d_in[6];
    float* out = (float*)d_out;

    (void)in_sizes; (void)n_in; (void)out_size;

    __nv_bfloat16 *xhi, *xlo, *whi, *wlo;
    cudaGetSymbolAddress((void**)&xhi, g_xhi);
    cudaGetSymbolAddress((void**)&xlo, g_xlo);
    cudaGetSymbolAddress((void**)&whi, g_whi);
    cudaGetSymbolAddress((void**)&wlo, g_wlo);

    convert_kernel<<<(B_ * S_ * D_) / 1024, 256>>>(X, xhi, xlo);
    convert_kernel<<<(D_ * D_) / 1024, 256>>>(Wq, whi + 0 * (size_t)D_ * D_, wlo + 0 * (size_t)D_ * D_);
    convert_kernel<<<(D_ * D_) / 1024, 256>>>(Wk, whi + 1 * (size_t)D_ * D_, wlo + 1 * (size_t)D_ * D_);
    convert_kernel<<<(D_ * D_) / 1024, 256>>>(Wv, whi + 2 * (size_t)D_ * D_, wlo + 2 * (size_t)D_ * D_);

    cudaFuncSetAttribute(qkv_kernel,
                         cudaFuncAttributeMaxDynamicSharedMemorySize, QKV_SMEM);
    dim3 gq(24, 64);
    qkv_kernel<<<gq, 256, QKV_SMEM>>>(bq, bk, bv);

    cudaFuncSetAttribute(attn_kernel,
                         cudaFuncAttributeMaxDynamicSharedMemorySize, ATTN_SMEM);
    dim3 ga(S_ / 64, H_, B_);
    attn_kernel<<<ga, 128, ATTN_SMEM>>>(out);
}